// round 12
// baseline (speedup 1.0000x reference)
#include <cuda_runtime.h>
#include <math.h>

#define Wd 128
#define Hd 128
#define Fd 1000
#define NCHUNK 8
#define FPC 125            // faces per chunk (8*125 = 1000, exact)
#define NV (FPC*3)         // 375 vertex tasks per chunk
#define NPIX (Wd*Hd)
#define NBLK 512           // 64 tiles x 8 chunks
#define EPSv 1e-10f
#define SIGMAv 1e-4f
#define BTH 0.0425f        // cull threshold (>= sqrt(TCUT))
#define TCUT 1.8e-3f       // exp(-18) < 2^-25: 1-p == 1.0f exactly in fp32
#define PXS (2.0f / 127.0f)

// -------- persistent scratch (no allocations allowed) --------
__device__ float  g_fnrm[Fd * 3];
__device__ float  g_fuv[Fd * 6];
__device__ float4 g_part[NCHUNK * NPIX];   // best_score, w0, w1, prod
__device__ int    g_pidx[NCHUNK * NPIX];
__device__ unsigned g_ticket[64];          // per-tile arrival counters (self-reset)

// ============================================================
// Single kernel, no global barrier:
//  Phase A: vertex-parallel transform (256 thr) -> per-face
//           setup + tile cull (125 thr); ALL blocks publish
//           their chunk's g_fnrm/g_fuv/normal1 (idempotent)
//  Phase B: in-order compaction + unrolled raster loop
//  Ticket:  8th block to finish a tile shades its 256 pixels
// ============================================================
__global__ __launch_bounds__(256, 5)
void render_fused(const float* __restrict__ pts,
                  const int*   __restrict__ faces,
                  const float* __restrict__ rot,
                  const float* __restrict__ pos,
                  const float* __restrict__ proj,
                  const float* __restrict__ uv,
                  const int*   __restrict__ ft,
                  const float* __restrict__ tex,
                  const float* __restrict__ light,
                  float* __restrict__ out)
{
    const int tid   = threadIdx.x;
    const int bid   = blockIdx.x;
    const int tile  = bid & 63;
    const int chunk = bid >> 6;
    const int f0 = chunk * FPC;
    const int tx = tile & 7, ty = tile >> 3;

    __shared__ float sv_sx[NV], sv_sy[NV];           // screen coords
    __shared__ float sv_px[NV], sv_py[NV], sv_pz[NV];// camera-space coords
    __shared__ float4 s1[FPC], s2[FPC], s3[FPC];
    __shared__ float4 c1[FPC], c2[FPC], c3[FPC];
    __shared__ int    sflag[FPC];
    __shared__ int    s_n;
    __shared__ int    s_win;

    // ---------------- Phase A1: vertex transforms (all 256 threads) -------
    {
        float R0 = rot[0], R1 = rot[1], R2 = rot[2];
        float R3 = rot[3], R4 = rot[4], R5 = rot[5];
        float R6 = rot[6], R7 = rot[7], R8 = rot[8];
        float cc0 = pos[0], cc1 = pos[1], cc2 = pos[2];
        float pj0 = proj[0], pj1 = proj[1], pj2 = proj[2];

        for (int t = tid; t < NV; t += 256) {
            int fl = t / 3;
            int k  = t - fl * 3;
            int vi = faces[(f0 + fl) * 3 + k];
            const float* p = pts + vi * 3;
            float d0 = p[0] - cc0, d1 = p[1] - cc1, d2 = p[2] - cc2;
            float x = R0 * d0 + R1 * d1 + R2 * d2;
            float y = R3 * d0 + R4 * d1 + R5 * d2;
            float z = R6 * d0 + R7 * d1 + R8 * d2;
            sv_px[t] = x; sv_py[t] = y; sv_pz[t] = z;
            float Z = z * pj2;
            sv_sx[t] = (x * pj0) / Z;
            sv_sy[t] = (y * pj1) / Z;
        }
    }
    __syncthreads();

    // ---------------- Phase A2: per-face setup + tile cull (125 thr) ------
    if (tid < FPC) {
        int f = f0 + tid;
        int vb = tid * 3;

        float p0x = sv_px[vb], p0y = sv_py[vb], p0z = sv_pz[vb];
        float p1x = sv_px[vb+1], p1y = sv_py[vb+1], p1z = sv_pz[vb+1];
        float p2x = sv_px[vb+2], p2y = sv_py[vb+2], p2z = sv_pz[vb+2];
        float x0s = sv_sx[vb],   y0s = sv_sy[vb];
        float x1s = sv_sx[vb+1], y1s = sv_sy[vb+1];
        float x2s = sv_sx[vb+2], y2s = sv_sy[vb+2];

        float ax = p1x - p0x, ay = p1y - p0y, az = p1z - p0z;
        float bx = p2x - p0x, by = p2y - p0y, bz = p2z - p0z;
        float nx = ay * bz - az * by;
        float ny = az * bx - ax * bz;
        float nz = ax * by - ay * bx;

        bool valid = nz > 0.0f;

        float A0  = x1s * y2s - x2s * y1s;
        float Bx0 = y1s - y2s;
        float By0 = x2s - x1s;
        float A1  = x2s * y0s - x0s * y2s;
        float Bx1 = y2s - y0s;
        float By1 = x0s - x2s;
        float A2  = x0s * y1s - x1s * y0s;
        float area = A0 + A1 + A2;
        bool areaok = fabsf(area) > EPSv;
        float ia = areaok ? (1.0f / area) : 0.0f;
        bool ok = valid && areaok;

        float4 v1 = ok ? make_float4(A0, Bx0, By0, ia)
                       : make_float4(-1e30f, 0.0f, 0.0f, 1.0f);
        float4 v2 = make_float4(A1, Bx1, By1, __int_as_float(f));
        s1[tid] = v1;
        s2[tid] = v2;
        s3[tid] = make_float4(p0z, p1z, p2z, 0.0f);

        // ALL blocks publish per-face globals for their chunk (idempotent,
        // identical values) so each tile's winner depends only on its own
        // 8 blocks.
        {
            float nn = sqrtf(nx * nx + ny * ny + nz * nz);
            float inv = 1.0f / fmaxf(nn, EPSv);
            float* onrm = out + NPIX * 3 + NPIX;
            onrm[f * 3 + 0] = nx * inv;
            onrm[f * 3 + 1] = ny * inv;
            onrm[f * 3 + 2] = nz * inv;
            g_fnrm[f * 3 + 0] = nx;
            g_fnrm[f * 3 + 1] = ny;
            g_fnrm[f * 3 + 2] = nz;
            #pragma unroll
            for (int k = 0; k < 3; k++) {
                int ti = ft[f * 3 + k];
                g_fuv[f * 6 + 2 * k + 0] = uv[ti * 2 + 0];
                g_fuv[f * 6 + 2 * k + 1] = uv[ti * 2 + 1];
            }
        }

        // tile cull via corner evaluation (b affine in px,py)
        float pxA = -1.0f + (float)(tx * 16)      * PXS;
        float pxB = -1.0f + (float)(tx * 16 + 15) * PXS;
        float pyA =  1.0f - (float)(ty * 16)      * PXS;
        float pyB =  1.0f - (float)(ty * 16 + 15) * PXS;

        float b0c[4], b1c[4];
        b0c[0] = (v1.x + pxA * v1.y + pyA * v1.z) * v1.w;
        b0c[1] = (v1.x + pxB * v1.y + pyA * v1.z) * v1.w;
        b0c[2] = (v1.x + pxA * v1.y + pyB * v1.z) * v1.w;
        b0c[3] = (v1.x + pxB * v1.y + pyB * v1.z) * v1.w;
        b1c[0] = (v2.x + pxA * v2.y + pyA * v2.z) * v1.w;
        b1c[1] = (v2.x + pxB * v2.y + pyA * v2.z) * v1.w;
        b1c[2] = (v2.x + pxA * v2.y + pyB * v2.z) * v1.w;
        b1c[3] = (v2.x + pxB * v2.y + pyB * v2.z) * v1.w;

        float m0 = fmaxf(fmaxf(b0c[0], b0c[1]), fmaxf(b0c[2], b0c[3]));
        float m1 = fmaxf(fmaxf(b1c[0], b1c[1]), fmaxf(b1c[2], b1c[3]));
        float s01min = fminf(fminf(b0c[0] + b1c[0], b0c[1] + b1c[1]),
                             fminf(b0c[2] + b1c[2], b0c[3] + b1c[3]));
        float m2 = 1.0f - s01min;
        sflag[tid] = (m0 >= -BTH) && (m1 >= -BTH) && (m2 >= -BTH);
    }
    __syncthreads();

    // ---------------- order-preserving compaction (warp 0) ---------------
    if (tid < 32) {
        int cnt = 0;
        #pragma unroll
        for (int r = 0; r < 4; r++) {
            int i = r * 32 + tid;
            bool p = (i < FPC) && (sflag[i] != 0);
            unsigned m = __ballot_sync(0xffffffffu, p);
            int ofs = cnt + __popc(m & ((1u << tid) - 1u));
            if (p) {
                c1[ofs] = s1[i];
                c2[ofs] = s2[i];   // .w carries global face id
                c3[ofs] = s3[i];
            }
            cnt += __popc(m);
        }
        if (tid == 0) s_n = cnt;
    }
    __syncthreads();

    // ---------------- Phase B: unrolled raster loop -----------------------
    {
        const int ns = s_n;
        int lx = tid & 15, ly = tid >> 4;
        int w = tx * 16 + lx;
        int h = ty * 16 + ly;
        float pxv = -1.0f + (float)w * PXS;
        float pyv =  1.0f - (float)h * PXS;

        float best = -1000000000.0f;
        int   bidx = f0;
        float bw0 = 0.0f, bw1 = 0.0f;
        float prod = 1.0f;

        #pragma unroll 4
        for (int i = 0; i < ns; i++) {
            float4 a = c1[i];
            float4 b = c2[i];
            float b0 = (a.x + pxv * a.y + pyv * a.z) * a.w;
            float b1 = (b.x + pxv * b.y + pyv * b.z) * a.w;
            float b2 = 1.0f - b0 - b1;
            float bmin = fminf(b0, fminf(b1, b2));

            float d = fmaxf(-bmin, 0.0f);
            float t = d * d;
            float fac = (t < TCUT) ? (1.0f - __expf(t * (-1.0f / SIGMAv))) : 1.0f;
            prod *= fac;

            if (bmin >= 0.0f) {
                float4 z = c3[i];
                float zp = b0 * z.x + b1 * z.y + b2 * z.z;
                if (zp > best) {       // ascending face order; strict > = argmax-first
                    best = zp; bidx = __float_as_int(b.w); bw0 = b0; bw1 = b1;
                }
            }
        }

        int pix = h * Wd + w;
        g_part[chunk * NPIX + pix] = make_float4(best, bw0, bw1, prod);
        g_pidx[chunk * NPIX + pix] = bidx;
    }

    // ---------------- per-tile ticket: 8th arriver shades -----------------
    __syncthreads();                       // all g_part writes in-flight done
    if (tid == 0) {
        __threadfence();                   // release this block's writes
        unsigned old = atomicAdd(&g_ticket[tile], 1u);
        s_win = (old == NCHUNK - 1);
        if (s_win) {
            g_ticket[tile] = 0u;           // reset for next launch
            __threadfence();               // acquire all 8 blocks' writes
        }
    }
    __syncthreads();
    if (!s_win) return;                    // 7 of 8 blocks exit early

    // ---------------- Phase C: winner shades its tile (256 px) ------------
    {
        int lx = tid & 15, ly = tid >> 4;
        int w = tx * 16 + lx;
        int h = ty * 16 + ly;
        int pix = h * Wd + w;

        float4 pc[NCHUNK];
        int    pi[NCHUNK];
        #pragma unroll
        for (int c = 0; c < NCHUNK; c++) {
            pc[c] = g_part[c * NPIX + pix];
            pi[c] = g_pidx[c * NPIX + pix];
        }

        float best = pc[0].x, w0 = pc[0].y, w1 = pc[0].z, prod = pc[0].w;
        int idx = pi[0];
        #pragma unroll
        for (int c = 1; c < NCHUNK; c++) {
            prod *= pc[c].w;
            if (pc[c].x > best) {      // strict > keeps earliest chunk on ties
                best = pc[c].x; w0 = pc[c].y; w1 = pc[c].z; idx = pi[c];
            }
        }
        float vis = (best > -5.0e8f) ? 1.0f : 0.0f;
        float w2 = 1.0f - w0 - w1;
        float sumw = w0 + w1 + w2;

        float nx = g_fnrm[idx * 3 + 0];
        float ny = g_fnrm[idx * 3 + 1];
        float nz = g_fnrm[idx * 3 + 2];
        float fnx = nx * sumw * vis;
        float fny = ny * sumw * vis;
        float fnz = nz * sumw * vis;

        const float* uvp = g_fuv + idx * 6;
        float u = (w0 * uvp[0] + w1 * uvp[2] + w2 * uvp[4]) * vis;
        float v = (w0 * uvp[1] + w1 * uvp[3] + w2 * uvp[5]) * vis;
        float hard = sumw * vis;

        float nn = sqrtf(fnx * fnx + fny * fny + fnz * fnz);
        float inv = 1.0f / fmaxf(nn, EPSv);
        float X = fnx * inv, Y = fny * inv, Z = fnz * inv;

        float shading =
            0.2820948f                    * __ldg(light + 0) +
            (0.4886025f * Y)              * __ldg(light + 1) +
            (0.4886025f * Z)              * __ldg(light + 2) +
            (0.4886025f * X)              * __ldg(light + 3) +
            (1.092548f * X * Y)           * __ldg(light + 4) +
            (1.092548f * Y * Z)           * __ldg(light + 5) +
            (0.3153916f * (3.0f * Z * Z - 1.0f)) * __ldg(light + 6) +
            (1.092548f * X * Z)           * __ldg(light + 7) +
            (0.5462742f * (X * X - Y * Y))* __ldg(light + 8);

        float uu = fminf(fmaxf(u, 0.0f), 1.0f) * 255.0f;
        float vv = fminf(fmaxf(v, 0.0f), 1.0f) * 255.0f;
        float x0f = floorf(uu), y0f = floorf(vv);
        int x0 = (int)x0f, y0 = (int)y0f;
        int x1 = min(x0 + 1, 255), y1 = min(y0 + 1, 255);
        float fx = uu - x0f, fy = vv - y0f;
        float omfx = 1.0f - fx, omfy = 1.0f - fy;

        #pragma unroll
        for (int c = 0; c < 3; c++) {
            const float* tc = tex + c * 65536;
            float c00 = __ldg(tc + y0 * 256 + x0);
            float c01 = __ldg(tc + y0 * 256 + x1);
            float c10 = __ldg(tc + y1 * 256 + x0);
            float c11 = __ldg(tc + y1 * 256 + x1);
            float col = (c00 * omfx + c01 * fx) * omfy + (c10 * omfx + c11 * fx) * fy;
            float r = col * shading * hard;
            out[pix * 3 + c] = fminf(fmaxf(r, 0.0f), 1.0f);
        }
        out[NPIX * 3 + pix] = 1.0f - prod;    // improb
    }
}

// ============================================================
// launch
// ============================================================
extern "C" void kernel_launch(void* const* d_in, const int* in_sizes, int n_in,
                              void* d_out, int out_size)
{
    const float* pts   = (const float*)d_in[0];   // (1,602,3)
    const int*   faces = (const int*)  d_in[1];   // (1000,3)
    const float* rot   = (const float*)d_in[2];   // (1,3,3)
    const float* pos   = (const float*)d_in[3];   // (1,3)
    const float* proj  = (const float*)d_in[4];   // (3,1)
    const float* uv    = (const float*)d_in[5];   // (1,602,2)
    const int*   ft    = (const int*)  d_in[6];   // (1000,3)
    const float* tex   = (const float*)d_in[7];   // (1,3,256,256)
    const float* light = (const float*)d_in[8];   // (1,9)

    float* out = (float*)d_out;
    // layout: imrender [0,49152) | improb [49152,65536) | normal1 [65536,68536)

    render_fused<<<NBLK, 256>>>(pts, faces, rot, pos, proj, uv, ft,
                                tex, light, out);
}

// round 13
// speedup vs baseline: 1.1119x; 1.1119x over previous
#include <cuda_runtime.h>
#include <math.h>

#define Wd 128
#define Hd 128
#define Fd 1000
#define NCHUNK 8
#define FPC 125            // faces per chunk (8*125 = 1000, exact)
#define NV (FPC*3)         // 375 vertex tasks per chunk
#define NPIX (Wd*Hd)
#define NBLK 512           // 64 tiles x 8 chunks
#define EPSv 1e-10f
#define SIGMAv 1e-4f
#define BTH 0.0425f        // cull threshold (>= sqrt(TCUT))
#define TCUT 1.8e-3f       // exp(-18) < 2^-25: 1-p == 1.0f exactly in fp32
#define PXS (2.0f / 127.0f)

// -------- persistent scratch (no allocations allowed) --------
__device__ float  g_fnrm[Fd * 3];
__device__ float  g_fuv[Fd * 6];
__device__ float4 g_part[NCHUNK * NPIX];   // best_score, w0, w1, prod
__device__ int    g_pidx[NCHUNK * NPIX];

// -------- hierarchical grid barrier (self-resetting, low contention) -----
__device__ unsigned g_c1[64];
__device__ unsigned g_c2[8];
__device__ unsigned g_croot = 0;
__device__ unsigned g_gen   = 0;

__device__ __forceinline__ void grid_barrier(int bid)
{
    __syncthreads();
    if (threadIdx.x == 0) {
        volatile unsigned* vgen = &g_gen;
        unsigned my = *vgen;               // read generation BEFORE arriving
        __threadfence();                   // release prior writes
        int g1 = bid >> 3;                 // 64 groups of 8
        if (atomicAdd(&g_c1[g1], 1u) == 7u) {
            g_c1[g1] = 0u;
            int g2 = g1 >> 3;              // 8 supergroups of 8
            if (atomicAdd(&g_c2[g2], 1u) == 7u) {
                g_c2[g2] = 0u;
                if (atomicAdd(&g_croot, 1u) == 7u) {
                    g_croot = 0u;
                    __threadfence();
                    atomicAdd(&g_gen, 1u); // release everyone
                }
            }
        }
        while (*vgen == my) { }
        __threadfence();                   // acquire
    }
    __syncthreads();
}

// ============================================================
// Single fused kernel (R9 structure, shortened critical path):
//  Phase A1: vertex transforms spread over all 256 threads
//  Phase A2: per-face setup + tile cull (125 threads)
//  Phase B : in-order compaction + unrolled raster loop
//  barrier (hierarchical)
//  Phase C : shade 32 px/block, batched reduction loads
// ============================================================
__global__ __launch_bounds__(256, 5)
void render_fused(const float* __restrict__ pts,
                  const int*   __restrict__ faces,
                  const float* __restrict__ rot,
                  const float* __restrict__ pos,
                  const float* __restrict__ proj,
                  const float* __restrict__ uv,
                  const int*   __restrict__ ft,
                  const float* __restrict__ tex,
                  const float* __restrict__ light,
                  float* __restrict__ out)
{
    const int tid   = threadIdx.x;
    const int bid   = blockIdx.x;
    const int tile  = bid & 63;
    const int chunk = bid >> 6;
    const int f0 = chunk * FPC;
    const int tx = tile & 7, ty = tile >> 3;

    __shared__ float sv_sx[NV], sv_sy[NV];            // screen coords
    __shared__ float sv_pz[NV];                       // camera-space z
    __shared__ float sv_px[NV], sv_py[NV];            // camera-space x,y
    __shared__ float4 s1[FPC], s2[FPC], s3[FPC];
    __shared__ float4 c1[FPC], c2[FPC], c3[FPC];
    __shared__ int    sflag[FPC];
    __shared__ int    s_n;

    // ---------------- Phase A1: vertex transforms (256 threads) -----------
    {
        float R0 = rot[0], R1 = rot[1], R2 = rot[2];
        float R3 = rot[3], R4 = rot[4], R5 = rot[5];
        float R6 = rot[6], R7 = rot[7], R8 = rot[8];
        float cc0 = pos[0], cc1 = pos[1], cc2 = pos[2];
        float pj0 = proj[0], pj1 = proj[1], pj2 = proj[2];

        for (int t = tid; t < NV; t += 256) {
            int fl = t / 3;
            int k  = t - fl * 3;
            int vi = faces[(f0 + fl) * 3 + k];
            const float* p = pts + vi * 3;
            float d0 = p[0] - cc0, d1 = p[1] - cc1, d2 = p[2] - cc2;
            float x = R0 * d0 + R1 * d1 + R2 * d2;
            float y = R3 * d0 + R4 * d1 + R5 * d2;
            float z = R6 * d0 + R7 * d1 + R8 * d2;
            sv_px[t] = x; sv_py[t] = y; sv_pz[t] = z;
            float Z = z * pj2;
            sv_sx[t] = (x * pj0) / Z;
            sv_sy[t] = (y * pj1) / Z;
        }
    }
    __syncthreads();

    // ---------------- Phase A2: per-face setup + tile cull (125 thr) ------
    if (tid < FPC) {
        int f = f0 + tid;
        int vb = tid * 3;

        float p0z = sv_pz[vb], p1z = sv_pz[vb+1], p2z = sv_pz[vb+2];
        float x0s = sv_sx[vb],   y0s = sv_sy[vb];
        float x1s = sv_sx[vb+1], y1s = sv_sy[vb+1];
        float x2s = sv_sx[vb+2], y2s = sv_sy[vb+2];

        float ax = sv_px[vb+1] - sv_px[vb], ay = sv_py[vb+1] - sv_py[vb], az = p1z - p0z;
        float bx = sv_px[vb+2] - sv_px[vb], by = sv_py[vb+2] - sv_py[vb], bz = p2z - p0z;
        float nx = ay * bz - az * by;
        float ny = az * bx - ax * bz;
        float nz = ax * by - ay * bx;

        bool valid = nz > 0.0f;

        float A0  = x1s * y2s - x2s * y1s;
        float Bx0 = y1s - y2s;
        float By0 = x2s - x1s;
        float A1  = x2s * y0s - x0s * y2s;
        float Bx1 = y2s - y0s;
        float By1 = x0s - x2s;
        float A2  = x0s * y1s - x1s * y0s;
        float area = A0 + A1 + A2;
        bool areaok = fabsf(area) > EPSv;
        float ia = areaok ? (1.0f / area) : 0.0f;
        bool ok = valid && areaok;

        float4 v1 = ok ? make_float4(A0, Bx0, By0, ia)
                       : make_float4(-1e30f, 0.0f, 0.0f, 1.0f);
        float4 v2 = make_float4(A1, Bx1, By1, __int_as_float(f));
        s1[tid] = v1;
        s2[tid] = v2;
        s3[tid] = make_float4(p0z, p1z, p2z, 0.0f);

        if (tile == 0) {   // single publisher per face (as in R9)
            float nn = sqrtf(nx * nx + ny * ny + nz * nz);
            float inv = 1.0f / fmaxf(nn, EPSv);
            float* onrm = out + NPIX * 3 + NPIX;
            onrm[f * 3 + 0] = nx * inv;
            onrm[f * 3 + 1] = ny * inv;
            onrm[f * 3 + 2] = nz * inv;
            g_fnrm[f * 3 + 0] = nx;
            g_fnrm[f * 3 + 1] = ny;
            g_fnrm[f * 3 + 2] = nz;
            #pragma unroll
            for (int k = 0; k < 3; k++) {
                int ti = ft[f * 3 + k];
                g_fuv[f * 6 + 2 * k + 0] = uv[ti * 2 + 0];
                g_fuv[f * 6 + 2 * k + 1] = uv[ti * 2 + 1];
            }
        }

        // tile cull via corner evaluation (b affine in px,py)
        float pxA = -1.0f + (float)(tx * 16)      * PXS;
        float pxB = -1.0f + (float)(tx * 16 + 15) * PXS;
        float pyA =  1.0f - (float)(ty * 16)      * PXS;
        float pyB =  1.0f - (float)(ty * 16 + 15) * PXS;

        float b0c[4], b1c[4];
        b0c[0] = (v1.x + pxA * v1.y + pyA * v1.z) * v1.w;
        b0c[1] = (v1.x + pxB * v1.y + pyA * v1.z) * v1.w;
        b0c[2] = (v1.x + pxA * v1.y + pyB * v1.z) * v1.w;
        b0c[3] = (v1.x + pxB * v1.y + pyB * v1.z) * v1.w;
        b1c[0] = (v2.x + pxA * v2.y + pyA * v2.z) * v1.w;
        b1c[1] = (v2.x + pxB * v2.y + pyA * v2.z) * v1.w;
        b1c[2] = (v2.x + pxA * v2.y + pyB * v2.z) * v1.w;
        b1c[3] = (v2.x + pxB * v2.y + pyB * v2.z) * v1.w;

        float m0 = fmaxf(fmaxf(b0c[0], b0c[1]), fmaxf(b0c[2], b0c[3]));
        float m1 = fmaxf(fmaxf(b1c[0], b1c[1]), fmaxf(b1c[2], b1c[3]));
        float s01min = fminf(fminf(b0c[0] + b1c[0], b0c[1] + b1c[1]),
                             fminf(b0c[2] + b1c[2], b0c[3] + b1c[3]));
        float m2 = 1.0f - s01min;
        sflag[tid] = (m0 >= -BTH) && (m1 >= -BTH) && (m2 >= -BTH);
    }
    __syncthreads();

    // ---------------- order-preserving compaction (warp 0) ---------------
    if (tid < 32) {
        int cnt = 0;
        #pragma unroll
        for (int r = 0; r < 4; r++) {
            int i = r * 32 + tid;
            bool p = (i < FPC) && (sflag[i] != 0);
            unsigned m = __ballot_sync(0xffffffffu, p);
            int ofs = cnt + __popc(m & ((1u << tid) - 1u));
            if (p) {
                c1[ofs] = s1[i];
                c2[ofs] = s2[i];   // .w carries global face id
                c3[ofs] = s3[i];
            }
            cnt += __popc(m);
        }
        if (tid == 0) s_n = cnt;
    }
    __syncthreads();

    // ---------------- Phase B: unrolled raster loop -----------------------
    {
        const int ns = s_n;
        int lx = tid & 15, ly = tid >> 4;
        int w = tx * 16 + lx;
        int h = ty * 16 + ly;
        float pxv = -1.0f + (float)w * PXS;
        float pyv =  1.0f - (float)h * PXS;

        float best = -1000000000.0f;
        int   bidx = f0;
        float bw0 = 0.0f, bw1 = 0.0f;
        float prod = 1.0f;

        #pragma unroll 4
        for (int i = 0; i < ns; i++) {
            float4 a = c1[i];
            float4 b = c2[i];
            float b0 = (a.x + pxv * a.y + pyv * a.z) * a.w;
            float b1 = (b.x + pxv * b.y + pyv * b.z) * a.w;
            float b2 = 1.0f - b0 - b1;
            float bmin = fminf(b0, fminf(b1, b2));

            float d = fmaxf(-bmin, 0.0f);
            float t = d * d;
            float fac = (t < TCUT) ? (1.0f - __expf(t * (-1.0f / SIGMAv))) : 1.0f;
            prod *= fac;

            if (bmin >= 0.0f) {
                float4 z = c3[i];
                float zp = b0 * z.x + b1 * z.y + b2 * z.z;
                if (zp > best) {       // ascending face order; strict > = argmax-first
                    best = zp; bidx = __float_as_int(b.w); bw0 = b0; bw1 = b1;
                }
            }
        }

        int pix = h * Wd + w;
        g_part[chunk * NPIX + pix] = make_float4(best, bw0, bw1, prod);
        g_pidx[chunk * NPIX + pix] = bidx;
    }

    grid_barrier(bid);

    // ---------------- Phase C: shade (warp 0, 32 pixels per block) --------
    if (tid < 32) {
        int pix = bid * 32 + tid;

        float4 pc[NCHUNK];
        int    pi[NCHUNK];
        #pragma unroll
        for (int c = 0; c < NCHUNK; c++) {
            pc[c] = g_part[c * NPIX + pix];
            pi[c] = g_pidx[c * NPIX + pix];
        }

        float best = pc[0].x, w0 = pc[0].y, w1 = pc[0].z, prod = pc[0].w;
        int idx = pi[0];
        #pragma unroll
        for (int c = 1; c < NCHUNK; c++) {
            prod *= pc[c].w;
            if (pc[c].x > best) {      // strict > keeps earliest chunk on ties
                best = pc[c].x; w0 = pc[c].y; w1 = pc[c].z; idx = pi[c];
            }
        }
        float vis = (best > -5.0e8f) ? 1.0f : 0.0f;
        float w2 = 1.0f - w0 - w1;
        float sumw = w0 + w1 + w2;

        float nx = g_fnrm[idx * 3 + 0];
        float ny = g_fnrm[idx * 3 + 1];
        float nz = g_fnrm[idx * 3 + 2];
        float fnx = nx * sumw * vis;
        float fny = ny * sumw * vis;
        float fnz = nz * sumw * vis;

        const float* uvp = g_fuv + idx * 6;
        float u = (w0 * uvp[0] + w1 * uvp[2] + w2 * uvp[4]) * vis;
        float v = (w0 * uvp[1] + w1 * uvp[3] + w2 * uvp[5]) * vis;
        float hard = sumw * vis;

        float nn = sqrtf(fnx * fnx + fny * fny + fnz * fnz);
        float inv = 1.0f / fmaxf(nn, EPSv);
        float X = fnx * inv, Y = fny * inv, Z = fnz * inv;

        float shading =
            0.2820948f                    * __ldg(light + 0) +
            (0.4886025f * Y)              * __ldg(light + 1) +
            (0.4886025f * Z)              * __ldg(light + 2) +
            (0.4886025f * X)              * __ldg(light + 3) +
            (1.092548f * X * Y)           * __ldg(light + 4) +
            (1.092548f * Y * Z)           * __ldg(light + 5) +
            (0.3153916f * (3.0f * Z * Z - 1.0f)) * __ldg(light + 6) +
            (1.092548f * X * Z)           * __ldg(light + 7) +
            (0.5462742f * (X * X - Y * Y))* __ldg(light + 8);

        float uu = fminf(fmaxf(u, 0.0f), 1.0f) * 255.0f;
        float vv = fminf(fmaxf(v, 0.0f), 1.0f) * 255.0f;
        float x0f = floorf(uu), y0f = floorf(vv);
        int x0 = (int)x0f, y0 = (int)y0f;
        int x1 = min(x0 + 1, 255), y1 = min(y0 + 1, 255);
        float fx = uu - x0f, fy = vv - y0f;
        float omfx = 1.0f - fx, omfy = 1.0f - fy;

        #pragma unroll
        for (int c = 0; c < 3; c++) {
            const float* tc = tex + c * 65536;
            float c00 = __ldg(tc + y0 * 256 + x0);
            float c01 = __ldg(tc + y0 * 256 + x1);
            float c10 = __ldg(tc + y1 * 256 + x0);
            float c11 = __ldg(tc + y1 * 256 + x1);
            float col = (c00 * omfx + c01 * fx) * omfy + (c10 * omfx + c11 * fx) * fy;
            float r = col * shading * hard;
            out[pix * 3 + c] = fminf(fmaxf(r, 0.0f), 1.0f);
        }
        out[NPIX * 3 + pix] = 1.0f - prod;    // improb
    }
}

// ============================================================
// launch
// ============================================================
extern "C" void kernel_launch(void* const* d_in, const int* in_sizes, int n_in,
                              void* d_out, int out_size)
{
    const float* pts   = (const float*)d_in[0];   // (1,602,3)
    const int*   faces = (const int*)  d_in[1];   // (1000,3)
    const float* rot   = (const float*)d_in[2];   // (1,3,3)
    const float* pos   = (const float*)d_in[3];   // (1,3)
    const float* proj  = (const float*)d_in[4];   // (3,1)
    const float* uv    = (const float*)d_in[5];   // (1,602,2)
    const int*   ft    = (const int*)  d_in[6];   // (1000,3)
    const float* tex   = (const float*)d_in[7];   // (1,3,256,256)
    const float* light = (const float*)d_in[8];   // (1,9)

    float* out = (float*)d_out;
    // layout: imrender [0,49152) | improb [49152,65536) | normal1 [65536,68536)

    render_fused<<<NBLK, 256>>>(pts, faces, rot, pos, proj, uv, ft,
                                tex, light, out);
}

// round 14
// speedup vs baseline: 1.1618x; 1.0448x over previous
#include <cuda_runtime.h>
#include <math.h>

#define Wd 128
#define Hd 128
#define Fd 1000
#define NCHUNK 8
#define FPC 125            // faces per chunk (8*125 = 1000, exact)
#define NPIX (Wd*Hd)
#define NBLK 512           // 64 tiles x 8 chunks
#define EPSv 1e-10f
#define SIGMAv 1e-4f
#define BTH 0.0425f        // cull threshold (>= sqrt(TCUT))
#define TCUT 1.8e-3f       // exp(-18) = 1.52e-8 < 2^-25: 1-p == 1.0f exactly
#define PXS (2.0f / 127.0f)

// -------- persistent scratch (no allocations allowed) --------
__device__ float  g_fnrm[Fd * 3];
__device__ float  g_fuv[Fd * 6];
__device__ float4 g_part[NCHUNK * NPIX];   // best_score, w0, w1, prod
__device__ int    g_pidx[NCHUNK * NPIX];

// -------- grid barrier (self-resetting each launch) --------
__device__ unsigned g_count = 0;
__device__ unsigned g_gen   = 0;

__device__ __forceinline__ void grid_barrier()
{
    __syncthreads();
    if (threadIdx.x == 0) {
        volatile unsigned* vgen = &g_gen;
        unsigned my = *vgen;
        __threadfence();
        unsigned arrived = atomicAdd(&g_count, 1);
        if (arrived == NBLK - 1) {
            g_count = 0;
            __threadfence();
            atomicAdd(&g_gen, 1);
        } else {
            while (*vgen == my) { }
            __threadfence();
        }
    }
    __syncthreads();
}

// ============================================================
// Single fused kernel (R9 champion + tighter bit-exact cull):
//  Phase A: per-block face setup of its 125-face chunk + tile cull
//  Phase B: in-order compaction + unrolled raster loop
//  barrier
//  Phase C: shade 32 px/block with batched reduction loads
// ============================================================
__global__ __launch_bounds__(256, 5)
void render_fused(const float* __restrict__ pts,
                  const int*   __restrict__ faces,
                  const float* __restrict__ rot,
                  const float* __restrict__ pos,
                  const float* __restrict__ proj,
                  const float* __restrict__ uv,
                  const int*   __restrict__ ft,
                  const float* __restrict__ tex,
                  const float* __restrict__ light,
                  float* __restrict__ out)
{
    const int tid   = threadIdx.x;
    const int bid   = blockIdx.x;
    const int tile  = bid & 63;
    const int chunk = bid >> 6;
    const int f0 = chunk * FPC;
    const int tx = tile & 7, ty = tile >> 3;

    __shared__ float4 s1[FPC], s2[FPC], s3[FPC];
    __shared__ float4 c1[FPC], c2[FPC], c3[FPC];
    __shared__ int    sflag[FPC];
    __shared__ int    s_n;

    // ---------------- Phase A: face setup + tile cull --------------------
    if (tid < FPC) {
        int f = f0 + tid;

        float R0 = rot[0], R1 = rot[1], R2 = rot[2];
        float R3 = rot[3], R4 = rot[4], R5 = rot[5];
        float R6 = rot[6], R7 = rot[7], R8 = rot[8];
        float cc0 = pos[0], cc1 = pos[1], cc2 = pos[2];
        float pj0 = proj[0], pj1 = proj[1], pj2 = proj[2];

        float pcx[3], pcy[3], pcz[3], sx[3], sy[3];
        #pragma unroll
        for (int k = 0; k < 3; k++) {
            int vi = faces[f * 3 + k];
            const float* p = pts + vi * 3;
            float d0 = p[0] - cc0, d1 = p[1] - cc1, d2 = p[2] - cc2;
            float x = R0 * d0 + R1 * d1 + R2 * d2;
            float y = R3 * d0 + R4 * d1 + R5 * d2;
            float z = R6 * d0 + R7 * d1 + R8 * d2;
            pcx[k] = x; pcy[k] = y; pcz[k] = z;
            float Z = z * pj2;
            sx[k] = (x * pj0) / Z;
            sy[k] = (y * pj1) / Z;
        }

        float ax = pcx[1] - pcx[0], ay = pcy[1] - pcy[0], az = pcz[1] - pcz[0];
        float bx = pcx[2] - pcx[0], by = pcy[2] - pcy[0], bz = pcz[2] - pcz[0];
        float nx = ay * bz - az * by;
        float ny = az * bx - ax * bz;
        float nz = ax * by - ay * bx;

        bool valid = nz > 0.0f;

        float A0  = sx[1] * sy[2] - sx[2] * sy[1];
        float Bx0 = sy[1] - sy[2];
        float By0 = sx[2] - sx[1];
        float A1  = sx[2] * sy[0] - sx[0] * sy[2];
        float Bx1 = sy[2] - sy[0];
        float By1 = sx[0] - sx[2];
        float A2  = sx[0] * sy[1] - sx[1] * sy[0];
        float area = A0 + A1 + A2;
        bool areaok = fabsf(area) > EPSv;
        float ia = areaok ? (1.0f / area) : 0.0f;
        bool ok = valid && areaok;

        float4 v1 = ok ? make_float4(A0, Bx0, By0, ia)
                       : make_float4(-1e30f, 0.0f, 0.0f, 1.0f);
        float4 v2 = make_float4(A1, Bx1, By1, __int_as_float(f));
        s1[tid] = v1;
        s2[tid] = v2;
        s3[tid] = make_float4(pcz[0], pcz[1], pcz[2], 0.0f);

        if (tile == 0) {
            float nn = sqrtf(nx * nx + ny * ny + nz * nz);
            float inv = 1.0f / fmaxf(nn, EPSv);
            float* onrm = out + NPIX * 3 + NPIX;
            onrm[f * 3 + 0] = nx * inv;
            onrm[f * 3 + 1] = ny * inv;
            onrm[f * 3 + 2] = nz * inv;
            g_fnrm[f * 3 + 0] = nx;
            g_fnrm[f * 3 + 1] = ny;
            g_fnrm[f * 3 + 2] = nz;
            #pragma unroll
            for (int k = 0; k < 3; k++) {
                int ti = ft[f * 3 + k];
                g_fuv[f * 6 + 2 * k + 0] = uv[ti * 2 + 0];
                g_fuv[f * 6 + 2 * k + 1] = uv[ti * 2 + 1];
            }
        }

        // tile cull via corner evaluation (b affine in px,py)
        float pxA = -1.0f + (float)(tx * 16)      * PXS;
        float pxB = -1.0f + (float)(tx * 16 + 15) * PXS;
        float pyA =  1.0f - (float)(ty * 16)      * PXS;
        float pyB =  1.0f - (float)(ty * 16 + 15) * PXS;

        float b0c[4], b1c[4];
        b0c[0] = (v1.x + pxA * v1.y + pyA * v1.z) * v1.w;
        b0c[1] = (v1.x + pxB * v1.y + pyA * v1.z) * v1.w;
        b0c[2] = (v1.x + pxA * v1.y + pyB * v1.z) * v1.w;
        b0c[3] = (v1.x + pxB * v1.y + pyB * v1.z) * v1.w;
        b1c[0] = (v2.x + pxA * v2.y + pyA * v2.z) * v1.w;
        b1c[1] = (v2.x + pxB * v2.y + pyA * v2.z) * v1.w;
        b1c[2] = (v2.x + pxA * v2.y + pyB * v2.z) * v1.w;
        b1c[3] = (v2.x + pxB * v2.y + pyB * v2.z) * v1.w;

        float m0 = fmaxf(fmaxf(b0c[0], b0c[1]), fmaxf(b0c[2], b0c[3]));
        float m1 = fmaxf(fmaxf(b1c[0], b1c[1]), fmaxf(b1c[2], b1c[3]));
        float s01min = fminf(fminf(b0c[0] + b1c[0], b0c[1] + b1c[1]),
                             fminf(b0c[2] + b1c[2], b0c[3] + b1c[3]));
        float m2 = 1.0f - s01min;
        sflag[tid] = (m0 >= -BTH) && (m1 >= -BTH) && (m2 >= -BTH);
    }
    __syncthreads();

    // ---------------- order-preserving compaction (warp 0) ---------------
    if (tid < 32) {
        int cnt = 0;
        #pragma unroll
        for (int r = 0; r < 4; r++) {
            int i = r * 32 + tid;
            bool p = (i < FPC) && (sflag[i] != 0);
            unsigned m = __ballot_sync(0xffffffffu, p);
            int ofs = cnt + __popc(m & ((1u << tid) - 1u));
            if (p) {
                c1[ofs] = s1[i];
                c2[ofs] = s2[i];   // .w carries global face id
                c3[ofs] = s3[i];
            }
            cnt += __popc(m);
        }
        if (tid == 0) s_n = cnt;
    }
    __syncthreads();

    // ---------------- Phase B: unrolled raster loop -----------------------
    {
        const int ns = s_n;
        int lx = tid & 15, ly = tid >> 4;
        int w = tx * 16 + lx;
        int h = ty * 16 + ly;
        float pxv = -1.0f + (float)w * PXS;
        float pyv =  1.0f - (float)h * PXS;

        float best = -1000000000.0f;
        int   bidx = f0;
        float bw0 = 0.0f, bw1 = 0.0f;
        float prod = 1.0f;

        #pragma unroll 4
        for (int i = 0; i < ns; i++) {
            float4 a = c1[i];
            float4 b = c2[i];
            float b0 = (a.x + pxv * a.y + pyv * a.z) * a.w;
            float b1 = (b.x + pxv * b.y + pyv * b.z) * a.w;
            float b2 = 1.0f - b0 - b1;
            float bmin = fminf(b0, fminf(b1, b2));

            float d = fmaxf(-bmin, 0.0f);
            float t = d * d;
            float fac = (t < TCUT) ? (1.0f - __expf(t * (-1.0f / SIGMAv))) : 1.0f;
            prod *= fac;

            if (bmin >= 0.0f) {
                float4 z = c3[i];
                float zp = b0 * z.x + b1 * z.y + b2 * z.z;
                if (zp > best) {       // ascending face order; strict > = argmax-first
                    best = zp; bidx = __float_as_int(b.w); bw0 = b0; bw1 = b1;
                }
            }
        }

        int pix = h * Wd + w;
        g_part[chunk * NPIX + pix] = make_float4(best, bw0, bw1, prod);
        g_pidx[chunk * NPIX + pix] = bidx;
    }

    grid_barrier();

    // ---------------- Phase C: shade (warp 0, 32 pixels per block) --------
    if (tid < 32) {
        int pix = bid * 32 + tid;

        // batched independent loads: one L2 round trip instead of 8 serial
        float4 pc[NCHUNK];
        int    pi[NCHUNK];
        #pragma unroll
        for (int c = 0; c < NCHUNK; c++) {
            pc[c] = g_part[c * NPIX + pix];
            pi[c] = g_pidx[c * NPIX + pix];
        }

        float best = pc[0].x, w0 = pc[0].y, w1 = pc[0].z, prod = pc[0].w;
        int idx = pi[0];
        #pragma unroll
        for (int c = 1; c < NCHUNK; c++) {
            prod *= pc[c].w;
            if (pc[c].x > best) {      // strict > keeps earliest chunk on ties
                best = pc[c].x; w0 = pc[c].y; w1 = pc[c].z; idx = pi[c];
            }
        }
        float vis = (best > -5.0e8f) ? 1.0f : 0.0f;
        float w2 = 1.0f - w0 - w1;
        float sumw = w0 + w1 + w2;

        float nx = g_fnrm[idx * 3 + 0];
        float ny = g_fnrm[idx * 3 + 1];
        float nz = g_fnrm[idx * 3 + 2];
        float fnx = nx * sumw * vis;
        float fny = ny * sumw * vis;
        float fnz = nz * sumw * vis;

        const float* uvp = g_fuv + idx * 6;
        float u = (w0 * uvp[0] + w1 * uvp[2] + w2 * uvp[4]) * vis;
        float v = (w0 * uvp[1] + w1 * uvp[3] + w2 * uvp[5]) * vis;
        float hard = sumw * vis;

        float nn = sqrtf(fnx * fnx + fny * fny + fnz * fnz);
        float inv = 1.0f / fmaxf(nn, EPSv);
        float X = fnx * inv, Y = fny * inv, Z = fnz * inv;

        float shading =
            0.2820948f                    * __ldg(light + 0) +
            (0.4886025f * Y)              * __ldg(light + 1) +
            (0.4886025f * Z)              * __ldg(light + 2) +
            (0.4886025f * X)              * __ldg(light + 3) +
            (1.092548f * X * Y)           * __ldg(light + 4) +
            (1.092548f * Y * Z)           * __ldg(light + 5) +
            (0.3153916f * (3.0f * Z * Z - 1.0f)) * __ldg(light + 6) +
            (1.092548f * X * Z)           * __ldg(light + 7) +
            (0.5462742f * (X * X - Y * Y))* __ldg(light + 8);

        float uu = fminf(fmaxf(u, 0.0f), 1.0f) * 255.0f;
        float vv = fminf(fmaxf(v, 0.0f), 1.0f) * 255.0f;
        float x0f = floorf(uu), y0f = floorf(vv);
        int x0 = (int)x0f, y0 = (int)y0f;
        int x1 = min(x0 + 1, 255), y1 = min(y0 + 1, 255);
        float fx = uu - x0f, fy = vv - y0f;
        float omfx = 1.0f - fx, omfy = 1.0f - fy;

        #pragma unroll
        for (int c = 0; c < 3; c++) {
            const float* tc = tex + c * 65536;
            float c00 = __ldg(tc + y0 * 256 + x0);
            float c01 = __ldg(tc + y0 * 256 + x1);
            float c10 = __ldg(tc + y1 * 256 + x0);
            float c11 = __ldg(tc + y1 * 256 + x1);
            float col = (c00 * omfx + c01 * fx) * omfy + (c10 * omfx + c11 * fx) * fy;
            float r = col * shading * hard;
            out[pix * 3 + c] = fminf(fmaxf(r, 0.0f), 1.0f);
        }
        out[NPIX * 3 + pix] = 1.0f - prod;    // improb
    }
}

// ============================================================
// launch
// ============================================================
extern "C" void kernel_launch(void* const* d_in, const int* in_sizes, int n_in,
                              void* d_out, int out_size)
{
    const float* pts   = (const float*)d_in[0];   // (1,602,3)
    const int*   faces = (const int*)  d_in[1];   // (1000,3)
    const float* rot   = (const float*)d_in[2];   // (1,3,3)
    const float* pos   = (const float*)d_in[3];   // (1,3)
    const float* proj  = (const float*)d_in[4];   // (3,1)
    const float* uv    = (const float*)d_in[5];   // (1,602,2)
    const int*   ft    = (const int*)  d_in[6];   // (1000,3)
    const float* tex   = (const float*)d_in[7];   // (1,3,256,256)
    const float* light = (const float*)d_in[8];   // (1,9)

    float* out = (float*)d_out;
    // layout: imrender [0,49152) | improb [49152,65536) | normal1 [65536,68536)

    render_fused<<<NBLK, 256>>>(pts, faces, rot, pos, proj, uv, ft,
                                tex, light, out);
}

// round 16
// speedup vs baseline: 1.3013x; 1.1201x over previous
#include <cuda_runtime.h>
#include <math.h>

#define Wd 128
#define Hd 128
#define Fd 1000
#define NCHUNK 8
#define FPC 125            // faces per chunk (8*125 = 1000, exact)
#define NPIX (Wd*Hd)
#define NBLK 512           // 64 tiles x 8 chunks
#define EPSv 1e-10f
#define SIGMAv 1e-4f
#define BTH 0.0425f        // cull threshold (>= sqrt(TCUT))
#define TCUT 1.8e-3f       // exp(-18) = 1.52e-8 < 2^-25: 1-p == 1.0f exactly
#define PXS (2.0f / 127.0f)

// -------- persistent scratch (no allocations allowed) --------
__device__ float  g_fnrm[Fd * 3];
__device__ float  g_fuv[Fd * 6];
__device__ float4 g_part[NCHUNK * NPIX];   // best_score, w0, w1, prod
__device__ int    g_pidx[NCHUNK * NPIX];

// -------- grid barrier (self-resetting each launch) --------
__device__ unsigned g_count = 0;
__device__ unsigned g_gen   = 0;

__device__ __forceinline__ void grid_barrier()
{
    __syncthreads();
    if (threadIdx.x == 0) {
        volatile unsigned* vgen = &g_gen;
        unsigned my = *vgen;
        __threadfence();
        unsigned arrived = atomicAdd(&g_count, 1);
        if (arrived == NBLK - 1) {
            g_count = 0;
            __threadfence();
            atomicAdd(&g_gen, 1);
        } else {
            while (*vgen == my) { }
            __threadfence();
        }
    }
    __syncthreads();
}

// ============================================================
// Single fused kernel (R14 champion + branchless raster loop):
//  Phase A: per-block face setup of its 125-face chunk + tile cull
//  Phase B: in-order compaction + BRANCHLESS unrolled raster loop
//  barrier
//  Phase C: shade 32 px/block with batched reduction loads
// ============================================================
__global__ __launch_bounds__(256, 5)
void render_fused(const float* __restrict__ pts,
                  const int*   __restrict__ faces,
                  const float* __restrict__ rot,
                  const float* __restrict__ pos,
                  const float* __restrict__ proj,
                  const float* __restrict__ uv,
                  const int*   __restrict__ ft,
                  const float* __restrict__ tex,
                  const float* __restrict__ light,
                  float* __restrict__ out)
{
    const int tid   = threadIdx.x;
    const int bid   = blockIdx.x;
    const int tile  = bid & 63;
    const int chunk = bid >> 6;
    const int f0 = chunk * FPC;
    const int tx = tile & 7, ty = tile >> 3;

    __shared__ float4 s1[FPC], s2[FPC], s3[FPC];
    __shared__ float4 c1[FPC], c2[FPC], c3[FPC];
    __shared__ int    sflag[FPC];
    __shared__ int    s_n;

    // ---------------- Phase A: face setup + tile cull --------------------
    if (tid < FPC) {
        int f = f0 + tid;

        float R0 = rot[0], R1 = rot[1], R2 = rot[2];
        float R3 = rot[3], R4 = rot[4], R5 = rot[5];
        float R6 = rot[6], R7 = rot[7], R8 = rot[8];
        float cc0 = pos[0], cc1 = pos[1], cc2 = pos[2];
        float pj0 = proj[0], pj1 = proj[1], pj2 = proj[2];

        float pcx[3], pcy[3], pcz[3], sx[3], sy[3];
        #pragma unroll
        for (int k = 0; k < 3; k++) {
            int vi = faces[f * 3 + k];
            const float* p = pts + vi * 3;
            float d0 = p[0] - cc0, d1 = p[1] - cc1, d2 = p[2] - cc2;
            float x = R0 * d0 + R1 * d1 + R2 * d2;
            float y = R3 * d0 + R4 * d1 + R5 * d2;
            float z = R6 * d0 + R7 * d1 + R8 * d2;
            pcx[k] = x; pcy[k] = y; pcz[k] = z;
            float Z = z * pj2;
            sx[k] = (x * pj0) / Z;
            sy[k] = (y * pj1) / Z;
        }

        float ax = pcx[1] - pcx[0], ay = pcy[1] - pcy[0], az = pcz[1] - pcz[0];
        float bx = pcx[2] - pcx[0], by = pcy[2] - pcy[0], bz = pcz[2] - pcz[0];
        float nx = ay * bz - az * by;
        float ny = az * bx - ax * bz;
        float nz = ax * by - ay * bx;

        bool valid = nz > 0.0f;

        float A0  = sx[1] * sy[2] - sx[2] * sy[1];
        float Bx0 = sy[1] - sy[2];
        float By0 = sx[2] - sx[1];
        float A1  = sx[2] * sy[0] - sx[0] * sy[2];
        float Bx1 = sy[2] - sy[0];
        float By1 = sx[0] - sx[2];
        float A2  = sx[0] * sy[1] - sx[1] * sy[0];
        float area = A0 + A1 + A2;
        bool areaok = fabsf(area) > EPSv;
        float ia = areaok ? (1.0f / area) : 0.0f;
        bool ok = valid && areaok;

        float4 v1 = ok ? make_float4(A0, Bx0, By0, ia)
                       : make_float4(-1e30f, 0.0f, 0.0f, 1.0f);
        float4 v2 = make_float4(A1, Bx1, By1, __int_as_float(f));
        s1[tid] = v1;
        s2[tid] = v2;
        s3[tid] = make_float4(pcz[0], pcz[1], pcz[2], 0.0f);

        if (tile == 0) {
            float nn = sqrtf(nx * nx + ny * ny + nz * nz);
            float inv = 1.0f / fmaxf(nn, EPSv);
            float* onrm = out + NPIX * 3 + NPIX;
            onrm[f * 3 + 0] = nx * inv;
            onrm[f * 3 + 1] = ny * inv;
            onrm[f * 3 + 2] = nz * inv;
            g_fnrm[f * 3 + 0] = nx;
            g_fnrm[f * 3 + 1] = ny;
            g_fnrm[f * 3 + 2] = nz;
            #pragma unroll
            for (int k = 0; k < 3; k++) {
                int ti = ft[f * 3 + k];
                g_fuv[f * 6 + 2 * k + 0] = uv[ti * 2 + 0];
                g_fuv[f * 6 + 2 * k + 1] = uv[ti * 2 + 1];
            }
        }

        // tile cull via corner evaluation (b affine in px,py)
        float pxA = -1.0f + (float)(tx * 16)      * PXS;
        float pxB = -1.0f + (float)(tx * 16 + 15) * PXS;
        float pyA =  1.0f - (float)(ty * 16)      * PXS;
        float pyB =  1.0f - (float)(ty * 16 + 15) * PXS;

        float b0c[4], b1c[4];
        b0c[0] = (v1.x + pxA * v1.y + pyA * v1.z) * v1.w;
        b0c[1] = (v1.x + pxB * v1.y + pyA * v1.z) * v1.w;
        b0c[2] = (v1.x + pxA * v1.y + pyB * v1.z) * v1.w;
        b0c[3] = (v1.x + pxB * v1.y + pyB * v1.z) * v1.w;
        b1c[0] = (v2.x + pxA * v2.y + pyA * v2.z) * v1.w;
        b1c[1] = (v2.x + pxB * v2.y + pyA * v2.z) * v1.w;
        b1c[2] = (v2.x + pxA * v2.y + pyB * v2.z) * v1.w;
        b1c[3] = (v2.x + pxB * v2.y + pyB * v2.z) * v1.w;

        float m0 = fmaxf(fmaxf(b0c[0], b0c[1]), fmaxf(b0c[2], b0c[3]));
        float m1 = fmaxf(fmaxf(b1c[0], b1c[1]), fmaxf(b1c[2], b1c[3]));
        float s01min = fminf(fminf(b0c[0] + b1c[0], b0c[1] + b1c[1]),
                             fminf(b0c[2] + b1c[2], b0c[3] + b1c[3]));
        float m2 = 1.0f - s01min;
        sflag[tid] = (m0 >= -BTH) && (m1 >= -BTH) && (m2 >= -BTH);
    }
    __syncthreads();

    // ---------------- order-preserving compaction (warp 0) ---------------
    if (tid < 32) {
        int cnt = 0;
        #pragma unroll
        for (int r = 0; r < 4; r++) {
            int i = r * 32 + tid;
            bool p = (i < FPC) && (sflag[i] != 0);
            unsigned m = __ballot_sync(0xffffffffu, p);
            int ofs = cnt + __popc(m & ((1u << tid) - 1u));
            if (p) {
                c1[ofs] = s1[i];
                c2[ofs] = s2[i];   // .w carries global face id
                c3[ofs] = s3[i];
            }
            cnt += __popc(m);
        }
        if (tid == 0) s_n = cnt;
    }
    __syncthreads();

    // ---------------- Phase B: BRANCHLESS unrolled raster loop ------------
    {
        const int ns = s_n;
        int lx = tid & 15, ly = tid >> 4;
        int w = tx * 16 + lx;
        int h = ty * 16 + ly;
        float pxv = -1.0f + (float)w * PXS;
        float pyv =  1.0f - (float)h * PXS;

        float best = -1000000000.0f;
        int   bidx = f0;
        float bw0 = 0.0f, bw1 = 0.0f;
        float prod = 1.0f;

        #pragma unroll 4
        for (int i = 0; i < ns; i++) {
            float4 a = c1[i];
            float4 b = c2[i];
            float4 z = c3[i];
            float b0 = (a.x + pxv * a.y + pyv * a.z) * a.w;
            float b1 = (b.x + pxv * b.y + pyv * b.z) * a.w;
            float b2 = 1.0f - b0 - b1;
            float bmin = fminf(b0, fminf(b1, b2));

            // improb factor: for t >= 1.8e-3, exp <= e^-18 < 2^-25 so
            // 1.0f - exp rounds to exactly 1.0f -> no guard needed.
            float d = fmaxf(-bmin, 0.0f);
            float t = d * d;
            float fac = 1.0f - __expf(t * (-1.0f / SIGMAv));
            prod *= fac;

            // branchless winner update (bit-identical selection semantics;
            // ascending face order + strict > = argmax-first tie-break)
            float zp = b0 * z.x + b1 * z.y + b2 * z.z;
            bool win = (bmin >= 0.0f) && (zp > best);
            best = win ? zp : best;
            bidx = win ? __float_as_int(b.w) : bidx;
            bw0  = win ? b0 : bw0;
            bw1  = win ? b1 : bw1;
        }

        int pix = h * Wd + w;
        g_part[chunk * NPIX + pix] = make_float4(best, bw0, bw1, prod);
        g_pidx[chunk * NPIX + pix] = bidx;
    }

    grid_barrier();

    // ---------------- Phase C: shade (warp 0, 32 pixels per block) --------
    if (tid < 32) {
        int pix = bid * 32 + tid;

        // batched independent loads: one L2 round trip instead of 8 serial
        float4 pc[NCHUNK];
        int    pi[NCHUNK];
        #pragma unroll
        for (int c = 0; c < NCHUNK; c++) {
            pc[c] = g_part[c * NPIX + pix];
            pi[c] = g_pidx[c * NPIX + pix];
        }

        float best = pc[0].x, w0 = pc[0].y, w1 = pc[0].z, prod = pc[0].w;
        int idx = pi[0];
        #pragma unroll
        for (int c = 1; c < NCHUNK; c++) {
            prod *= pc[c].w;
            if (pc[c].x > best) {      // strict > keeps earliest chunk on ties
                best = pc[c].x; w0 = pc[c].y; w1 = pc[c].z; idx = pi[c];
            }
        }
        float vis = (best > -5.0e8f) ? 1.0f : 0.0f;
        float w2 = 1.0f - w0 - w1;
        float sumw = w0 + w1 + w2;

        float nx = g_fnrm[idx * 3 + 0];
        float ny = g_fnrm[idx * 3 + 1];
        float nz = g_fnrm[idx * 3 + 2];
        float fnx = nx * sumw * vis;
        float fny = ny * sumw * vis;
        float fnz = nz * sumw * vis;

        const float* uvp = g_fuv + idx * 6;
        float u = (w0 * uvp[0] + w1 * uvp[2] + w2 * uvp[4]) * vis;
        float v = (w0 * uvp[1] + w1 * uvp[3] + w2 * uvp[5]) * vis;
        float hard = sumw * vis;

        float nn = sqrtf(fnx * fnx + fny * fny + fnz * fnz);
        float inv = 1.0f / fmaxf(nn, EPSv);
        float X = fnx * inv, Y = fny * inv, Z = fnz * inv;

        float shading =
            0.2820948f                    * __ldg(light + 0) +
            (0.4886025f * Y)              * __ldg(light + 1) +
            (0.4886025f * Z)              * __ldg(light + 2) +
            (0.4886025f * X)              * __ldg(light + 3) +
            (1.092548f * X * Y)           * __ldg(light + 4) +
            (1.092548f * Y * Z)           * __ldg(light + 5) +
            (0.3153916f * (3.0f * Z * Z - 1.0f)) * __ldg(light + 6) +
            (1.092548f * X * Z)           * __ldg(light + 7) +
            (0.5462742f * (X * X - Y * Y))* __ldg(light + 8);

        float uu = fminf(fmaxf(u, 0.0f), 1.0f) * 255.0f;
        float vv = fminf(fmaxf(v, 0.0f), 1.0f) * 255.0f;
        float x0f = floorf(uu), y0f = floorf(vv);
        int x0 = (int)x0f, y0 = (int)y0f;
        int x1 = min(x0 + 1, 255), y1 = min(y0 + 1, 255);
        float fx = uu - x0f, fy = vv - y0f;
        float omfx = 1.0f - fx, omfy = 1.0f - fy;

        #pragma unroll
        for (int c = 0; c < 3; c++) {
            const float* tc = tex + c * 65536;
            float c00 = __ldg(tc + y0 * 256 + x0);
            float c01 = __ldg(tc + y0 * 256 + x1);
            float c10 = __ldg(tc + y1 * 256 + x0);
            float c11 = __ldg(tc + y1 * 256 + x1);
            float col = (c00 * omfx + c01 * fx) * omfy + (c10 * omfx + c11 * fx) * fy;
            float r = col * shading * hard;
            out[pix * 3 + c] = fminf(fmaxf(r, 0.0f), 1.0f);
        }
        out[NPIX * 3 + pix] = 1.0f - prod;    // improb
    }
}

// ============================================================
// launch
// ============================================================
extern "C" void kernel_launch(void* const* d_in, const int* in_sizes, int n_in,
                              void* d_out, int out_size)
{
    const float* pts   = (const float*)d_in[0];   // (1,602,3)
    const int*   faces = (const int*)  d_in[1];   // (1000,3)
    const float* rot   = (const float*)d_in[2];   // (1,3,3)
    const float* pos   = (const float*)d_in[3];   // (1,3)
    const float* proj  = (const float*)d_in[4];   // (3,1)
    const float* uv    = (const float*)d_in[5];   // (1,602,2)
    const int*   ft    = (const int*)  d_in[6];   // (1000,3)
    const float* tex   = (const float*)d_in[7];   // (1,3,256,256)
    const float* light = (const float*)d_in[8];   // (1,9)

    float* out = (float*)d_out;
    // layout: imrender [0,49152) | improb [49152,65536) | normal1 [65536,68536)

    render_fused<<<NBLK, 256>>>(pts, faces, rot, pos, proj, uv, ft,
                                tex, light, out);
}

// round 17
// speedup vs baseline: 1.3274x; 1.0200x over previous
#include <cuda_runtime.h>
#include <math.h>

#define Wd 128
#define Hd 128
#define Fd 1000
#define NCHUNK 8
#define FPC 125            // faces per chunk (8*125 = 1000, exact)
#define NPIX (Wd*Hd)
#define NBLK 512           // 64 tiles x 8 chunks
#define EPSv 1e-10f
#define SIGMAv 1e-4f
#define BTH 0.0425f        // cull threshold (>= sqrt(TCUT)=0.04243 + slack)
#define TCUT 1.8e-3f       // exp(-18) = 1.52e-8 < 2^-25: 1-p == 1.0f exactly
#define PXS (2.0f / 127.0f)

// -------- persistent scratch (no allocations allowed) --------
__device__ float  g_fnrm[Fd * 3];
__device__ float  g_fuv[Fd * 6];
__device__ float4 g_part[NCHUNK * NPIX];   // best_score, w0, w1, prod
__device__ int    g_pidx[NCHUNK * NPIX];

// -------- grid barrier (self-resetting each launch) --------
__device__ unsigned g_count = 0;
__device__ unsigned g_gen   = 0;

__device__ __forceinline__ void grid_barrier()
{
    __syncthreads();
    if (threadIdx.x == 0) {
        volatile unsigned* vgen = &g_gen;
        unsigned my = *vgen;
        __threadfence();
        unsigned arrived = atomicAdd(&g_count, 1);
        if (arrived == NBLK - 1) {
            g_count = 0;
            __threadfence();
            atomicAdd(&g_gen, 1);
        } else {
            while (*vgen == my) { }
            __threadfence();
        }
    }
    __syncthreads();
}

// ============================================================
// Single fused kernel (R16 champion + per-warp STRIP culling):
//  Phase A: face setup + per-strip (16x2) conservative cull masks
//  Phase B: per-warp ballot-compacted index list + branchless loop
//  barrier
//  Phase C: shade 32 px/block with batched reduction loads
// ============================================================
__global__ __launch_bounds__(256, 5)
void render_fused(const float* __restrict__ pts,
                  const int*   __restrict__ faces,
                  const float* __restrict__ rot,
                  const float* __restrict__ pos,
                  const float* __restrict__ proj,
                  const float* __restrict__ uv,
                  const int*   __restrict__ ft,
                  const float* __restrict__ tex,
                  const float* __restrict__ light,
                  float* __restrict__ out)
{
    const int tid   = threadIdx.x;
    const int bid   = blockIdx.x;
    const int tile  = bid & 63;
    const int chunk = bid >> 6;
    const int f0 = chunk * FPC;
    const int tx = tile & 7, ty = tile >> 3;
    const int lane = tid & 31;
    const int wrp  = tid >> 5;

    __shared__ float4 s1[FPC], s2[FPC], s3[FPC];
    __shared__ int    smask[FPC];           // 8-bit strip survival mask
    __shared__ int    slist[8 * 128];       // per-strip survivor indices

    // ---------------- Phase A: face setup + strip cull masks --------------
    if (tid < FPC) {
        int f = f0 + tid;

        float R0 = rot[0], R1 = rot[1], R2 = rot[2];
        float R3 = rot[3], R4 = rot[4], R5 = rot[5];
        float R6 = rot[6], R7 = rot[7], R8 = rot[8];
        float cc0 = pos[0], cc1 = pos[1], cc2 = pos[2];
        float pj0 = proj[0], pj1 = proj[1], pj2 = proj[2];

        float pcx[3], pcy[3], pcz[3], sx[3], sy[3];
        #pragma unroll
        for (int k = 0; k < 3; k++) {
            int vi = faces[f * 3 + k];
            const float* p = pts + vi * 3;
            float d0 = p[0] - cc0, d1 = p[1] - cc1, d2 = p[2] - cc2;
            float x = R0 * d0 + R1 * d1 + R2 * d2;
            float y = R3 * d0 + R4 * d1 + R5 * d2;
            float z = R6 * d0 + R7 * d1 + R8 * d2;
            pcx[k] = x; pcy[k] = y; pcz[k] = z;
            float Z = z * pj2;
            sx[k] = (x * pj0) / Z;
            sy[k] = (y * pj1) / Z;
        }

        float ax = pcx[1] - pcx[0], ay = pcy[1] - pcy[0], az = pcz[1] - pcz[0];
        float bx = pcx[2] - pcx[0], by = pcy[2] - pcy[0], bz = pcz[2] - pcz[0];
        float nx = ay * bz - az * by;
        float ny = az * bx - ax * bz;
        float nz = ax * by - ay * bx;

        bool valid = nz > 0.0f;

        float A0  = sx[1] * sy[2] - sx[2] * sy[1];
        float Bx0 = sy[1] - sy[2];
        float By0 = sx[2] - sx[1];
        float A1  = sx[2] * sy[0] - sx[0] * sy[2];
        float Bx1 = sy[2] - sy[0];
        float By1 = sx[0] - sx[2];
        float A2  = sx[0] * sy[1] - sx[1] * sy[0];
        float area = A0 + A1 + A2;
        bool areaok = fabsf(area) > EPSv;
        float ia = areaok ? (1.0f / area) : 0.0f;
        bool ok = valid && areaok;

        float4 v1 = ok ? make_float4(A0, Bx0, By0, ia)
                       : make_float4(-1e30f, 0.0f, 0.0f, 1.0f);
        float4 v2 = make_float4(A1, Bx1, By1, 0.0f);
        s1[tid] = v1;
        s2[tid] = v2;
        s3[tid] = make_float4(pcz[0], pcz[1], pcz[2], 0.0f);

        if (tile == 0) {
            float nn = sqrtf(nx * nx + ny * ny + nz * nz);
            float inv = 1.0f / fmaxf(nn, EPSv);
            float* onrm = out + NPIX * 3 + NPIX;
            onrm[f * 3 + 0] = nx * inv;
            onrm[f * 3 + 1] = ny * inv;
            onrm[f * 3 + 2] = nz * inv;
            g_fnrm[f * 3 + 0] = nx;
            g_fnrm[f * 3 + 1] = ny;
            g_fnrm[f * 3 + 2] = nz;
            #pragma unroll
            for (int k = 0; k < 3; k++) {
                int ti = ft[f * 3 + k];
                g_fuv[f * 6 + 2 * k + 0] = uv[ti * 2 + 0];
                g_fuv[f * 6 + 2 * k + 1] = uv[ti * 2 + 1];
            }
        }

        // ----- per-strip cull: b affine in (px,py); strip s = rows 2s,2s+1.
        // For each edge, value at (px, py_hi(s)) is affine in s with step
        // st = -2*PXS*By*ia; row-lo adds half-step hf; max over the strip's
        // 4 corners = max(A-end, B-end) + max(half,0).
        float pxA = -1.0f + (float)(tx * 16)      * PXS;
        float pxB = -1.0f + (float)(tx * 16 + 15) * PXS;
        float py0 =  1.0f - (float)(ty * 16)      * PXS;

        float iaW = v1.w;
        float e0A = (v1.x + pxA * v1.y + py0 * v1.z) * iaW;
        float e0B = (v1.x + pxB * v1.y + py0 * v1.z) * iaW;
        float st0 = -2.0f * PXS * v1.z * iaW;
        float hf0 = fmaxf(-PXS * v1.z * iaW, 0.0f);

        float e1A = (v2.x + pxA * v2.y + py0 * v2.z) * iaW;
        float e1B = (v2.x + pxB * v2.y + py0 * v2.z) * iaW;
        float st1 = -2.0f * PXS * v2.z * iaW;
        float hf1 = fmaxf(-PXS * v2.z * iaW, 0.0f);

        float sAq = e0A + e1A;
        float sBq = e0B + e1B;
        float sst = st0 + st1;
        float shf = fminf(-PXS * v1.z * iaW + (-PXS * v2.z * iaW), 0.0f);

        int mask = 0;
        #pragma unroll
        for (int s = 0; s < 8; s++) {
            float fs = (float)s;
            float m0 = fmaxf(fmaf(fs, st0, e0A), fmaf(fs, st0, e0B)) + hf0;
            float m1 = fmaxf(fmaf(fs, st1, e1A), fmaf(fs, st1, e1B)) + hf1;
            float sm = fminf(fmaf(fs, sst, sAq), fmaf(fs, sst, sBq)) + shf;
            float m2 = 1.0f - sm;
            bool alive = (m0 >= -BTH) && (m1 >= -BTH) && (m2 >= -BTH);
            mask |= (alive ? 1 : 0) << s;
        }
        smask[tid] = mask;
    }
    __syncthreads();

    // ---------------- per-warp strip list build (ballot compaction) -------
    int myn = 0;
    {
        #pragma unroll
        for (int r = 0; r < 4; r++) {
            int i = r * 32 + lane;
            bool p = (i < FPC) && ((smask[i] >> wrp) & 1);
            unsigned m = __ballot_sync(0xffffffffu, p);
            if (p) slist[wrp * 128 + myn + __popc(m & ((1u << lane) - 1u))] = i;
            myn += __popc(m);
        }
        __syncwarp();
    }

    // ---------------- Phase B: branchless raster over strip list ----------
    {
        int lx = tid & 15, ly = tid >> 4;   // ly = 2*wrp + (lane>>4)
        int w = tx * 16 + lx;
        int h = ty * 16 + ly;
        float pxv = -1.0f + (float)w * PXS;
        float pyv =  1.0f - (float)h * PXS;

        float best = -1000000000.0f;
        int   islot = 0;
        float bw0 = 0.0f, bw1 = 0.0f;
        float prod = 1.0f;

        const int* mylist = slist + wrp * 128;

        #pragma unroll 4
        for (int j = 0; j < myn; j++) {
            int i = mylist[j];
            float4 a = s1[i];
            float4 b = s2[i];
            float4 z = s3[i];
            float b0 = (a.x + pxv * a.y + pyv * a.z) * a.w;
            float b1 = (b.x + pxv * b.y + pyv * b.z) * a.w;
            float b2 = 1.0f - b0 - b1;
            float bmin = fminf(b0, fminf(b1, b2));

            // culled faces would have fac == 1.0f exactly (t >= TCUT)
            float d = fmaxf(-bmin, 0.0f);
            float t = d * d;
            float fac = 1.0f - __expf(t * (-1.0f / SIGMAv));
            prod *= fac;

            // branchless winner update; ascending i = ascending face id
            float zp = b0 * z.x + b1 * z.y + b2 * z.z;
            bool win = (bmin >= 0.0f) && (zp > best);
            best  = win ? zp : best;
            islot = win ? i : islot;
            bw0   = win ? b0 : bw0;
            bw1   = win ? b1 : bw1;
        }

        int pix = h * Wd + w;
        g_part[chunk * NPIX + pix] = make_float4(best, bw0, bw1, prod);
        g_pidx[chunk * NPIX + pix] = f0 + islot;
    }

    grid_barrier();

    // ---------------- Phase C: shade (warp 0, 32 pixels per block) --------
    if (tid < 32) {
        int pix = bid * 32 + tid;

        float4 pc[NCHUNK];
        int    pi[NCHUNK];
        #pragma unroll
        for (int c = 0; c < NCHUNK; c++) {
            pc[c] = g_part[c * NPIX + pix];
            pi[c] = g_pidx[c * NPIX + pix];
        }

        float best = pc[0].x, w0 = pc[0].y, w1 = pc[0].z, prod = pc[0].w;
        int idx = pi[0];
        #pragma unroll
        for (int c = 1; c < NCHUNK; c++) {
            prod *= pc[c].w;
            if (pc[c].x > best) {      // strict > keeps earliest chunk on ties
                best = pc[c].x; w0 = pc[c].y; w1 = pc[c].z; idx = pi[c];
            }
        }
        float vis = (best > -5.0e8f) ? 1.0f : 0.0f;
        float w2 = 1.0f - w0 - w1;
        float sumw = w0 + w1 + w2;

        float nx = g_fnrm[idx * 3 + 0];
        float ny = g_fnrm[idx * 3 + 1];
        float nz = g_fnrm[idx * 3 + 2];
        float fnx = nx * sumw * vis;
        float fny = ny * sumw * vis;
        float fnz = nz * sumw * vis;

        const float* uvp = g_fuv + idx * 6;
        float u = (w0 * uvp[0] + w1 * uvp[2] + w2 * uvp[4]) * vis;
        float v = (w0 * uvp[1] + w1 * uvp[3] + w2 * uvp[5]) * vis;
        float hard = sumw * vis;

        float nn = sqrtf(fnx * fnx + fny * fny + fnz * fnz);
        float inv = 1.0f / fmaxf(nn, EPSv);
        float X = fnx * inv, Y = fny * inv, Z = fnz * inv;

        float shading =
            0.2820948f                    * __ldg(light + 0) +
            (0.4886025f * Y)              * __ldg(light + 1) +
            (0.4886025f * Z)              * __ldg(light + 2) +
            (0.4886025f * X)              * __ldg(light + 3) +
            (1.092548f * X * Y)           * __ldg(light + 4) +
            (1.092548f * Y * Z)           * __ldg(light + 5) +
            (0.3153916f * (3.0f * Z * Z - 1.0f)) * __ldg(light + 6) +
            (1.092548f * X * Z)           * __ldg(light + 7) +
            (0.5462742f * (X * X - Y * Y))* __ldg(light + 8);

        float uu = fminf(fmaxf(u, 0.0f), 1.0f) * 255.0f;
        float vv = fminf(fmaxf(v, 0.0f), 1.0f) * 255.0f;
        float x0f = floorf(uu), y0f = floorf(vv);
        int x0 = (int)x0f, y0 = (int)y0f;
        int x1 = min(x0 + 1, 255), y1 = min(y0 + 1, 255);
        float fx = uu - x0f, fy = vv - y0f;
        float omfx = 1.0f - fx, omfy = 1.0f - fy;

        #pragma unroll
        for (int c = 0; c < 3; c++) {
            const float* tc = tex + c * 65536;
            float c00 = __ldg(tc + y0 * 256 + x0);
            float c01 = __ldg(tc + y0 * 256 + x1);
            float c10 = __ldg(tc + y1 * 256 + x0);
            float c11 = __ldg(tc + y1 * 256 + x1);
            float col = (c00 * omfx + c01 * fx) * omfy + (c10 * omfx + c11 * fx) * fy;
            float r = col * shading * hard;
            out[pix * 3 + c] = fminf(fmaxf(r, 0.0f), 1.0f);
        }
        out[NPIX * 3 + pix] = 1.0f - prod;    // improb
    }
}

// ============================================================
// launch
// ============================================================
extern "C" void kernel_launch(void* const* d_in, const int* in_sizes, int n_in,
                              void* d_out, int out_size)
{
    const float* pts   = (const float*)d_in[0];   // (1,602,3)
    const int*   faces = (const int*)  d_in[1];   // (1000,3)
    const float* rot   = (const float*)d_in[2];   // (1,3,3)
    const float* pos   = (const float*)d_in[3];   // (1,3)
    const float* proj  = (const float*)d_in[4];   // (3,1)
    const float* uv    = (const float*)d_in[5];   // (1,602,2)
    const int*   ft    = (const int*)  d_in[6];   // (1000,3)
    const float* tex   = (const float*)d_in[7];   // (1,3,256,256)
    const float* light = (const float*)d_in[8];   // (1,9)

    float* out = (float*)d_out;
    // layout: imrender [0,49152) | improb [49152,65536) | normal1 [65536,68536)

    render_fused<<<NBLK, 256>>>(pts, faces, rot, pos, proj, uv, ft,
                                tex, light, out);
}